// round 1
// baseline (speedup 1.0000x reference)
#include <cuda_runtime.h>

#define HEADS   16
#define S_LEN   2048
#define D_MODEL 1024
#define HD      64
#define BATCH   2
#define BH      (BATCH*HEADS)     // 32
#define R_SZ    257
#define WIN     128

// Scratch (allocation-free rule: device globals)
__device__ float g_Q[BH * S_LEN * HD];
__device__ float g_K[BH * S_LEN * HD];
__device__ float g_V[BH * S_LEN * HD];
__device__ float g_RP[BH * S_LEN * R_SZ];   // ~67 MB

// ---------------------------------------------------------------------------
// Kernel 1: QKV projection.  C[m,n] = sum_k X[m,k]*W[n,k] + b[n]
// M=4096, N=3072, K=1024.  128x128x8 tiles, 256 threads, 8x8 per thread.
// Scatter n -> (head, q/k/v, channel) into g_Q/g_K/g_V [bh][s][64].
// ---------------------------------------------------------------------------
__global__ __launch_bounds__(256)
void qkv_kernel(const float* __restrict__ X, const float* __restrict__ W,
                const float* __restrict__ bias) {
    __shared__ float As[8][128];
    __shared__ float Bs[8][128];
    const int bx = blockIdx.x;      // n tile: 0..23
    const int by = blockIdx.y;      // m tile: 0..31
    const int tid = threadIdx.x;
    const int tx = tid & 15, ty = tid >> 4;

    const int arow = tid >> 1;           // 0..127
    const int acol = (tid & 1) * 4;      // 0 or 4
    const float* Ag = X + (by * 128 + arow) * 1024 + acol;
    const float* Bg = W + (bx * 128 + arow) * 1024 + acol;

    float acc[8][8];
    #pragma unroll
    for (int i = 0; i < 8; i++)
        #pragma unroll
        for (int j = 0; j < 8; j++) acc[i][j] = 0.f;

    for (int k0 = 0; k0 < 1024; k0 += 8) {
        float4 a = *(const float4*)(Ag + k0);
        float4 b = *(const float4*)(Bg + k0);
        As[acol + 0][arow] = a.x; As[acol + 1][arow] = a.y;
        As[acol + 2][arow] = a.z; As[acol + 3][arow] = a.w;
        Bs[acol + 0][arow] = b.x; Bs[acol + 1][arow] = b.y;
        Bs[acol + 2][arow] = b.z; Bs[acol + 3][arow] = b.w;
        __syncthreads();
        #pragma unroll
        for (int kk = 0; kk < 8; kk++) {
            float ar[8], br[8];
            *(float4*)&ar[0] = *(const float4*)&As[kk][ty * 8];
            *(float4*)&ar[4] = *(const float4*)&As[kk][ty * 8 + 4];
            *(float4*)&br[0] = *(const float4*)&Bs[kk][tx * 8];
            *(float4*)&br[4] = *(const float4*)&Bs[kk][tx * 8 + 4];
            #pragma unroll
            for (int i = 0; i < 8; i++)
                #pragma unroll
                for (int j = 0; j < 8; j++)
                    acc[i][j] = fmaf(ar[i], br[j], acc[i][j]);
        }
        __syncthreads();
    }

    const int m_base = by * 128 + ty * 8;
    const int n_base = bx * 128 + tx * 8;
    #pragma unroll
    for (int i = 0; i < 8; i++) {
        const int m  = m_base + i;
        const int bb = m >> 11;           // batch
        const int sp = m & 2047;          // seq pos
        #pragma unroll
        for (int j = 0; j < 8; j++) {
            const int n   = n_base + j;
            const float v = acc[i][j] + __ldg(&bias[n]);
            const int head = n / 192;
            const int rem  = n - head * 192;
            const int t    = rem >> 6;    // 0=q 1=k 2=v
            const int c    = rem & 63;
            float* dst = (t == 0) ? g_Q : (t == 1) ? g_K : g_V;
            dst[((bb * HEADS + head) * S_LEN + sp) * HD + c] = v;
        }
    }
}

// ---------------------------------------------------------------------------
// Kernel 2: rp[bh][i][r] = q[bh][i] . Wr[r] + br[r]      (R=257, K=64)
// Block: 64 queries of one (b,h); 256 threads (16x16), 4x4 per thread;
// loop over 5 r-tiles of 64 (last tile covers r=256 only, guarded).
// ---------------------------------------------------------------------------
__global__ __launch_bounds__(256)
void rp_kernel(const float* __restrict__ Wr, const float* __restrict__ br) {
    __shared__ float Qs[64 * 64];     // [i][c]  (natural: a-frag reads broadcast)
    __shared__ float Ws[64 * 65];     // [r][c]  padded
    __shared__ float brs[64];

    const int st = blockIdx.x;        // 0..31 query tile
    const int bh = blockIdx.y;        // 0..31
    const int tid = threadIdx.x;
    const int tx = tid & 15, ty = tid >> 4;
    const int i0 = ty * 4, r0 = tx * 4;
    const int q_base = st * 64;

    const float* Qg = g_Q + (bh * S_LEN + q_base) * HD;
    #pragma unroll
    for (int l = 0; l < 4; l++) {
        int idx = tid + l * 256;          // float4 index
        int row = idx >> 4;
        int c4  = (idx & 15) * 4;
        *(float4*)&Qs[row * 64 + c4] = *(const float4*)(Qg + row * 64 + c4);
    }

    for (int rt = 0; rt < 5; rt++) {
        const int r_base = rt * 64;
        #pragma unroll
        for (int l = 0; l < 4; l++) {
            int idx = tid + l * 256;
            int row = idx >> 4;
            int c4  = (idx & 15) * 4;
            int r   = r_base + row;
            float4 v = make_float4(0.f, 0.f, 0.f, 0.f);
            if (r < R_SZ) v = *(const float4*)(Wr + r * 64 + c4);
            float* d = &Ws[row * 65 + c4];
            d[0] = v.x; d[1] = v.y; d[2] = v.z; d[3] = v.w;
        }
        if (tid < 64) {
            int r = r_base + tid;
            brs[tid] = (r < R_SZ) ? __ldg(&br[r]) : 0.f;
        }
        __syncthreads();

        float acc[4][4];
        #pragma unroll
        for (int i = 0; i < 4; i++)
            #pragma unroll
            for (int j = 0; j < 4; j++) acc[i][j] = 0.f;

        #pragma unroll 8
        for (int c = 0; c < 64; c++) {
            float a[4], bfr[4];
            #pragma unroll
            for (int i = 0; i < 4; i++) a[i]   = Qs[(i0 + i) * 64 + c];
            #pragma unroll
            for (int j = 0; j < 4; j++) bfr[j] = Ws[(r0 + j) * 65 + c];
            #pragma unroll
            for (int i = 0; i < 4; i++)
                #pragma unroll
                for (int j = 0; j < 4; j++)
                    acc[i][j] = fmaf(a[i], bfr[j], acc[i][j]);
        }

        #pragma unroll
        for (int i = 0; i < 4; i++) {
            const int ig = q_base + i0 + i;
            #pragma unroll
            for (int j = 0; j < 4; j++) {
                const int r = r_base + r0 + j;
                if (r < R_SZ)
                    g_RP[(bh * S_LEN + ig) * R_SZ + r] = acc[i][j] + brs[r0 + j];
            }
        }
        __syncthreads();
    }
}

// ---------------------------------------------------------------------------
// Kernel 3: flash attention with relative-position bias, fp32.
// Block = (bh, q-tile of 128). Key tiles of 64. 256 threads (16x16),
// S tile 128x64 -> 8x4 per thread; O tile 128x64 channels -> same mapping.
// ---------------------------------------------------------------------------
#define AT_SMEM_FLOATS (128*64 + 64*65 + 64*64 + 128*64)

__global__ __launch_bounds__(256, 2)
void attn_kernel(float* __restrict__ out) {
    extern __shared__ float sm[];
    float* Qs = sm;                       // [128][64]
    float* Ks = Qs + 128 * 64;            // [64][65]
    float* Vs = Ks + 64 * 65;             // [64][64]
    float* Ps = Vs + 64 * 64;             // [128][64]

    const int qt  = blockIdx.x;           // 0..15
    const int bh  = blockIdx.y;           // 0..31
    const int tid = threadIdx.x;
    const int tx = tid & 15, ty = tid >> 4;
    const int i0 = ty * 8;                // query rows in tile
    const int j0 = tx * 4;                // key cols in tile / out channels
    const int q_base = qt * 128;

    const float* Qg = g_Q + (bh * S_LEN + q_base) * HD;
    #pragma unroll
    for (int l = 0; l < 8; l++) {
        int idx = tid + l * 256;
        int row = idx >> 4;
        int c4  = (idx & 15) * 4;
        *(float4*)&Qs[row * 64 + c4] = *(const float4*)(Qg + row * 64 + c4);
    }

    float m_r[8], l_r[8], O[8][4];
    #pragma unroll
    for (int r = 0; r < 8; r++) {
        m_r[r] = -1e30f; l_r[r] = 0.f;
        #pragma unroll
        for (int c = 0; c < 4; c++) O[r][c] = 0.f;
    }

    const float* rpBH = g_RP + (size_t)(bh * S_LEN) * R_SZ;

    for (int jt = 0; jt < S_LEN / 64; jt++) {
        const int k_base = jt * 64;
        // load K (padded, scalar writes) and V (float4)
        #pragma unroll
        for (int l = 0; l < 4; l++) {
            int idx = tid + l * 256;
            int row = idx >> 4;
            int c4  = (idx & 15) * 4;
            float4 kv = *(const float4*)(g_K + ((size_t)(bh * S_LEN + k_base + row)) * HD + c4);
            float* d  = &Ks[row * 65 + c4];
            d[0] = kv.x; d[1] = kv.y; d[2] = kv.z; d[3] = kv.w;
            float4 vv = *(const float4*)(g_V + ((size_t)(bh * S_LEN + k_base + row)) * HD + c4);
            *(float4*)&Vs[row * 64 + c4] = vv;
        }
        __syncthreads();

        // S = Q K^T
        float S[8][4];
        #pragma unroll
        for (int r = 0; r < 8; r++)
            #pragma unroll
            for (int c = 0; c < 4; c++) S[r][c] = 0.f;

        #pragma unroll 8
        for (int kk = 0; kk < 64; kk++) {
            float a[8], b[4];
            #pragma unroll
            for (int r = 0; r < 8; r++) a[r] = Qs[(i0 + r) * 64 + kk];
            #pragma unroll
            for (int c = 0; c < 4; c++) b[c] = Ks[(j0 + c) * 65 + kk];
            #pragma unroll
            for (int r = 0; r < 8; r++)
                #pragma unroll
                for (int c = 0; c < 4; c++)
                    S[r][c] = fmaf(a[r], b[c], S[r][c]);
        }

        // scale + relative-position bias
        #pragma unroll
        for (int r = 0; r < 8; r++) {
            const int ig = q_base + i0 + r;
            const float* rr = rpBH + (size_t)ig * R_SZ;
            #pragma unroll
            for (int c = 0; c < 4; c++) {
                int o = (k_base + j0 + c) - ig;
                o = (o < -WIN) ? -WIN : (o > WIN ? WIN : o);
                S[r][c] = S[r][c] * 0.125f + __ldg(rr + o + WIN);
            }
        }

        // online softmax (row reductions across the 16 tx lanes)
        #pragma unroll
        for (int r = 0; r < 8; r++) {
            float mx = S[r][0];
            #pragma unroll
            for (int c = 1; c < 4; c++) mx = fmaxf(mx, S[r][c]);
            #pragma unroll
            for (int msk = 8; msk >= 1; msk >>= 1)
                mx = fmaxf(mx, __shfl_xor_sync(0xffffffffu, mx, msk));
            const float mnew = fmaxf(m_r[r], mx);
            const float corr = __expf(m_r[r] - mnew);
            float rs = 0.f;
            #pragma unroll
            for (int c = 0; c < 4; c++) {
                S[r][c] = __expf(S[r][c] - mnew);
                rs += S[r][c];
            }
            #pragma unroll
            for (int msk = 8; msk >= 1; msk >>= 1)
                rs += __shfl_xor_sync(0xffffffffu, rs, msk);
            l_r[r] = l_r[r] * corr + rs;
            m_r[r] = mnew;
            #pragma unroll
            for (int c = 0; c < 4; c++) O[r][c] *= corr;
            #pragma unroll
            for (int c = 0; c < 4; c++) Ps[(i0 + r) * 64 + j0 + c] = S[r][c];
        }
        __syncthreads();

        // O += P V
        #pragma unroll 8
        for (int j = 0; j < 64; j++) {
            float a[8];
            #pragma unroll
            for (int r = 0; r < 8; r++) a[r] = Ps[(i0 + r) * 64 + j];
            float4 b = *(const float4*)&Vs[j * 64 + j0];
            #pragma unroll
            for (int r = 0; r < 8; r++) {
                O[r][0] = fmaf(a[r], b.x, O[r][0]);
                O[r][1] = fmaf(a[r], b.y, O[r][1]);
                O[r][2] = fmaf(a[r], b.z, O[r][2]);
                O[r][3] = fmaf(a[r], b.w, O[r][3]);
            }
        }
        __syncthreads();
    }

    // epilogue: out[b][sp][h*64 + c]
    const int bb = bh >> 4, hh = bh & 15;
    #pragma unroll
    for (int r = 0; r < 8; r++) {
        const float inv = 1.f / l_r[r];
        const int ig = q_base + i0 + r;
        float4 o4 = make_float4(O[r][0] * inv, O[r][1] * inv,
                                O[r][2] * inv, O[r][3] * inv);
        *(float4*)&out[((size_t)(bb * S_LEN + ig)) * D_MODEL + hh * HD + j0] = o4;
    }
}

// ---------------------------------------------------------------------------
extern "C" void kernel_launch(void* const* d_in, const int* in_sizes, int n_in,
                              void* d_out, int out_size) {
    (void)in_sizes; (void)n_in; (void)out_size;
    const float* x    = (const float*)d_in[0];
    const float* Wqkv = (const float*)d_in[1];
    const float* bqkv = (const float*)d_in[2];
    const float* Wr   = (const float*)d_in[3];
    const float* br   = (const float*)d_in[4];
    float* out = (float*)d_out;

    dim3 g1(24, 32);
    qkv_kernel<<<g1, 256>>>(x, Wqkv, bqkv);

    dim3 g2(32, 32);
    rp_kernel<<<g2, 256>>>(Wr, br);

    const int smem_bytes = AT_SMEM_FLOATS * (int)sizeof(float);   // 98560
    cudaFuncSetAttribute(attn_kernel, cudaFuncAttributeMaxDynamicSharedMemorySize,
                         smem_bytes);
    dim3 g3(16, 32);
    attn_kernel<<<g3, 256, smem_bytes>>>(out);
}

// round 5
// speedup vs baseline: 2.0045x; 2.0045x over previous
#include <cuda_runtime.h>
#include <cuda_bf16.h>
#include <cstdint>

#define HEADS   16
#define S_LEN   2048
#define D_MODEL 1024
#define HD      64
#define BATCH   2
#define BH      (BATCH*HEADS)     // 32
#define R_SZ    257
#define WIN     128

// Scratch (allocation-free rule: device globals)
__device__ float g_Q[BH * S_LEN * HD];
__device__ float g_K[BH * S_LEN * HD];
__device__ float g_V[BH * S_LEN * HD];
__device__ float g_RP[BH * S_LEN * R_SZ];   // ~67 MB

// ===========================================================================
// Helpers: mma.sync bf16 (HMMA, arch-portable), ldmatrix, bf16 split packs
// ===========================================================================
__device__ __forceinline__ uint32_t smem_u32(const void* p) {
    uint32_t a;
    asm("{ .reg .u64 t; cvta.to.shared.u64 t, %1; cvt.u32.u64 %0, t; }"
        : "=r"(a) : "l"(p));
    return a;
}

__device__ __forceinline__ void ldsm4(uint32_t* r, uint32_t a) {
    asm volatile("ldmatrix.sync.aligned.m8n8.x4.shared.b16 {%0,%1,%2,%3}, [%4];"
                 : "=r"(r[0]), "=r"(r[1]), "=r"(r[2]), "=r"(r[3]) : "r"(a));
}
__device__ __forceinline__ void ldsm4t(uint32_t* r, uint32_t a) {
    asm volatile("ldmatrix.sync.aligned.m8n8.x4.trans.shared.b16 {%0,%1,%2,%3}, [%4];"
                 : "=r"(r[0]), "=r"(r[1]), "=r"(r[2]), "=r"(r[3]) : "r"(a));
}
__device__ __forceinline__ void mma_bf(float* c, uint32_t a0, uint32_t a1,
                                       uint32_t a2, uint32_t a3,
                                       uint32_t b0, uint32_t b1) {
    asm volatile("mma.sync.aligned.m16n8k16.row.col.f32.bf16.bf16.f32 "
                 "{%0,%1,%2,%3}, {%4,%5,%6,%7}, {%8,%9}, {%0,%1,%2,%3};"
                 : "+f"(c[0]), "+f"(c[1]), "+f"(c[2]), "+f"(c[3])
                 : "r"(a0), "r"(a1), "r"(a2), "r"(a3), "r"(b0), "r"(b1));
}

__device__ __forceinline__ uint32_t packbf(float lo, float hi) {
    uint32_t r;
    asm("cvt.rn.bf16x2.f32 %0, %1, %2;" : "=r"(r) : "f"(hi), "f"(lo));
    return r;
}
__device__ __forceinline__ float unlo(uint32_t p) { return __uint_as_float(p << 16); }
__device__ __forceinline__ float unhi(uint32_t p) { return __uint_as_float(p & 0xFFFF0000u); }

__device__ __forceinline__ void sts2(uint32_t a, uint32_t x, uint32_t y) {
    asm volatile("st.shared.v2.b32 [%0], {%1,%2};" :: "r"(a), "r"(x), "r"(y) : "memory");
}

// Store float4 (tile row r, col c, c%4==0) as bf16 hi+mid tiles, 128B-row swizzle.
// Rows are exactly 128B -> swizzle reduces to XOR of bits[4:6] by (r&7).
__device__ __forceinline__ void cvt_store(uint32_t hbase, uint32_t mbase,
                                          int r, int c, float4 v) {
    uint32_t off = (uint32_t)r * 128u + (((uint32_t)c * 2u) ^ (((uint32_t)r & 7u) << 4));
    uint32_t h0 = packbf(v.x, v.y), h1 = packbf(v.z, v.w);
    uint32_t m0 = packbf(v.x - unlo(h0), v.y - unhi(h0));
    uint32_t m1 = packbf(v.z - unlo(h1), v.w - unhi(h1));
    sts2(hbase + off, h0, h1);
    sts2(mbase + off, m0, m1);
}

__device__ __forceinline__ uint32_t sw_off(int row, int colb) {
    return (uint32_t)row * 128u + (((uint32_t)colb) ^ (((uint32_t)row & 7u) << 4));
}

// ===========================================================================
// Kernel 1: QKV projection, mma.sync bf16 3-term split.
// C[4096,3072] = X @ Wqkv^T + b, scattered into g_Q/g_K/g_V.
// CTA 128x128, k-chunk 64, 8 warps (4x2), warp tile 32x64.
// ===========================================================================
#define QKV_SMEM_B (4 * 16384)

__global__ __launch_bounds__(256, 2)
void qkv_mma_kernel(const float* __restrict__ X, const float* __restrict__ W,
                    const float* __restrict__ bias) {
    extern __shared__ char qsm[];
    const uint32_t base = smem_u32(qsm);
    const uint32_t Ah = base, Am = base + 16384, Bh = base + 32768, Bm = base + 49152;

    const int tid = threadIdx.x;
    const int lane = tid & 31, wid = tid >> 5;
    const int wm = wid & 3, wn = wid >> 2;
    const int bx = blockIdx.x % 24, by = blockIdx.x / 24;
    const int m0 = by * 128, n0 = bx * 128;
    const int lrow = lane & 15, lcolb = (lane >> 4) * 16;

    const int lr = tid >> 1;
    const int lcs = (tid & 1) * 32;
    const float* Arow = X + (size_t)(m0 + lr) * 1024 + lcs;
    const float* Brow = W + (size_t)(n0 + lr) * 1024 + lcs;

    float c[16][4];
    #pragma unroll
    for (int i = 0; i < 16; i++)
        #pragma unroll
        for (int j = 0; j < 4; j++) c[i][j] = 0.f;

    for (int kc = 0; kc < 16; kc++) {
        const int k0 = kc * 64;
        __syncthreads();
        #pragma unroll
        for (int q = 0; q < 8; q++) {
            float4 va = *(const float4*)(Arow + k0 + q * 4);
            cvt_store(Ah, Am, lr, lcs + q * 4, va);
            float4 vb = *(const float4*)(Brow + k0 + q * 4);
            cvt_store(Bh, Bm, lr, lcs + q * 4, vb);
        }
        __syncthreads();

        #pragma unroll
        for (int ks = 0; ks < 4; ks++) {
            const int colb = ks * 32 + lcolb;
            uint32_t ah[2][4], am2[2][4], bb[4][4];
            #pragma unroll
            for (int mf = 0; mf < 2; mf++) {
                const uint32_t off = sw_off(wm * 32 + mf * 16 + lrow, colb);
                ldsm4(ah[mf], Ah + off);
                ldsm4(am2[mf], Am + off);
            }
            #pragma unroll
            for (int nb = 0; nb < 4; nb++)
                ldsm4(bb[nb], Bh + sw_off(wn * 64 + nb * 16 + lrow, colb));
            #pragma unroll
            for (int mf = 0; mf < 2; mf++)
                #pragma unroll
                for (int nb = 0; nb < 4; nb++) {
                    mma_bf(c[mf * 8 + 2 * nb],     ah[mf][0], ah[mf][1], ah[mf][2], ah[mf][3], bb[nb][0], bb[nb][2]);
                    mma_bf(c[mf * 8 + 2 * nb + 1], ah[mf][0], ah[mf][1], ah[mf][2], ah[mf][3], bb[nb][1], bb[nb][3]);
                    mma_bf(c[mf * 8 + 2 * nb],     am2[mf][0], am2[mf][1], am2[mf][2], am2[mf][3], bb[nb][0], bb[nb][2]);
                    mma_bf(c[mf * 8 + 2 * nb + 1], am2[mf][0], am2[mf][1], am2[mf][2], am2[mf][3], bb[nb][1], bb[nb][3]);
                }
            #pragma unroll
            for (int nb = 0; nb < 4; nb++)
                ldsm4(bb[nb], Bm + sw_off(wn * 64 + nb * 16 + lrow, colb));
            #pragma unroll
            for (int mf = 0; mf < 2; mf++)
                #pragma unroll
                for (int nb = 0; nb < 4; nb++) {
                    mma_bf(c[mf * 8 + 2 * nb],     ah[mf][0], ah[mf][1], ah[mf][2], ah[mf][3], bb[nb][0], bb[nb][2]);
                    mma_bf(c[mf * 8 + 2 * nb + 1], ah[mf][0], ah[mf][1], ah[mf][2], ah[mf][3], bb[nb][1], bb[nb][3]);
                }
        }
    }

    // Epilogue: scatter with head/type decode.
    const int g = lane >> 2, t = lane & 3;
    #pragma unroll
    for (int mf = 0; mf < 2; mf++) {
        const int mr0 = m0 + wm * 32 + mf * 16 + g;
        const int bb0 = mr0 >> 11, sp0 = mr0 & 2047;
        const int sp1 = (mr0 + 8) & 2047;
        #pragma unroll
        for (int nf = 0; nf < 8; nf++) {
            const int n = n0 + wn * 64 + nf * 8 + t * 2;
            const float2 bv = *(const float2*)(bias + n);
            const int head = n / 192;
            const int rem  = n - head * 192;
            const int type = rem >> 6;
            const int c64  = rem & 63;
            float* dst = (type == 0) ? g_Q : (type == 1) ? g_K : g_V;
            const size_t b0i = ((size_t)((bb0 * HEADS + head) * S_LEN + sp0)) * HD + c64;
            const size_t b1i = ((size_t)((bb0 * HEADS + head) * S_LEN + sp1)) * HD + c64;
            float* ci = c[mf * 8 + nf];
            *(float2*)&dst[b0i] = make_float2(ci[0] + bv.x, ci[1] + bv.y);
            *(float2*)&dst[b1i] = make_float2(ci[2] + bv.x, ci[3] + bv.y);
        }
    }
}

// ---------------------------------------------------------------------------
// Kernel 2: rp[bh][i][r] = q[bh][i] . Wr[r] + br[r]   (fp32 FFMA, exact)
// ---------------------------------------------------------------------------
__global__ __launch_bounds__(256)
void rp_kernel(const float* __restrict__ Wr, const float* __restrict__ br) {
    __shared__ float Qs[64 * 64];
    __shared__ float Ws[64 * 65];
    __shared__ float brs[64];

    const int st = blockIdx.x;
    const int bh = blockIdx.y;
    const int tid = threadIdx.x;
    const int tx = tid & 15, ty = tid >> 4;
    const int i0 = ty * 4, r0 = tx * 4;
    const int q_base = st * 64;

    const float* Qg = g_Q + (bh * S_LEN + q_base) * HD;
    #pragma unroll
    for (int l = 0; l < 4; l++) {
        int idx = tid + l * 256;
        int row = idx >> 4;
        int c4  = (idx & 15) * 4;
        *(float4*)&Qs[row * 64 + c4] = *(const float4*)(Qg + row * 64 + c4);
    }

    for (int rt = 0; rt < 5; rt++) {
        const int r_base = rt * 64;
        #pragma unroll
        for (int l = 0; l < 4; l++) {
            int idx = tid + l * 256;
            int row = idx >> 4;
            int c4  = (idx & 15) * 4;
            int r   = r_base + row;
            float4 v = make_float4(0.f, 0.f, 0.f, 0.f);
            if (r < R_SZ) v = *(const float4*)(Wr + r * 64 + c4);
            float* d = &Ws[row * 65 + c4];
            d[0] = v.x; d[1] = v.y; d[2] = v.z; d[3] = v.w;
        }
        if (tid < 64) {
            int r = r_base + tid;
            brs[tid] = (r < R_SZ) ? __ldg(&br[r]) : 0.f;
        }
        __syncthreads();

        float acc[4][4];
        #pragma unroll
        for (int i = 0; i < 4; i++)
            #pragma unroll
            for (int j = 0; j < 4; j++) acc[i][j] = 0.f;

        #pragma unroll 8
        for (int c = 0; c < 64; c++) {
            float a[4], bfr[4];
            #pragma unroll
            for (int i = 0; i < 4; i++) a[i]   = Qs[(i0 + i) * 64 + c];
            #pragma unroll
            for (int j = 0; j < 4; j++) bfr[j] = Ws[(r0 + j) * 65 + c];
            #pragma unroll
            for (int i = 0; i < 4; i++)
                #pragma unroll
                for (int j = 0; j < 4; j++)
                    acc[i][j] = fmaf(a[i], bfr[j], acc[i][j]);
        }

        #pragma unroll
        for (int i = 0; i < 4; i++) {
            const int ig = q_base + i0 + i;
            #pragma unroll
            for (int j = 0; j < 4; j++) {
                const int r = r_base + r0 + j;
                if (r < R_SZ)
                    g_RP[(bh * S_LEN + ig) * R_SZ + r] = acc[i][j] + brs[r0 + j];
            }
        }
        __syncthreads();
    }
}

// ===========================================================================
// Kernel 3: flash attention, mma.sync bf16 3-term split for QK^T and PV.
// CTA: (bh, 128 q rows). 8 warps, warp = 16 q rows. Key tiles of 64.
// ===========================================================================
#define ATT_SMEM_B (2 * 16384 + 4 * 8192)   // Qh,Qm,Kh,Km,Vh,Vm = 64KB

__global__ __launch_bounds__(256, 2)
void attn_mma_kernel(float* __restrict__ out) {
    extern __shared__ char asm_[];
    const uint32_t base = smem_u32(asm_);
    const uint32_t Qh = base, Qm = base + 16384;
    const uint32_t Kh = base + 32768, Km = base + 40960;
    const uint32_t Vh = base + 49152, Vm = base + 57344;

    const int qt = blockIdx.x, bh = blockIdx.y;
    const int q0 = qt * 128;
    const int tid = threadIdx.x;
    const int lane = tid & 31, wid = tid >> 5;
    const int g = lane >> 2, t = lane & 3;
    const int lrow = lane & 15, lcolb = (lane >> 4) * 16;

    // Load + convert Q tile (128x64)
    {
        const int r = tid >> 1;
        const int cs = (tid & 1) * 32;
        const float* Qg = g_Q + ((size_t)(bh * S_LEN + q0 + r)) * HD + cs;
        #pragma unroll
        for (int q = 0; q < 8; q++)
            cvt_store(Qh, Qm, r, cs + q * 4, *(const float4*)(Qg + q * 4));
    }

    float o[8][4];
    #pragma unroll
    for (int i = 0; i < 8; i++)
        #pragma unroll
        for (int j = 0; j < 4; j++) o[i][j] = 0.f;
    float macc[2] = {-1e30f, -1e30f};
    float lacc[2] = {0.f, 0.f};

    const int i0 = q0 + wid * 16 + g;
    const int i1 = i0 + 8;
    const float* rpb0 = g_RP + ((size_t)(bh * S_LEN + i0)) * R_SZ + WIN;
    const float* rpb1 = g_RP + ((size_t)(bh * S_LEN + i1)) * R_SZ + WIN;

    const int lr = tid >> 2;
    const int lcs = (tid & 3) * 16;
    const float* Kg0 = g_K + ((size_t)(bh * S_LEN + lr)) * HD + lcs;
    const float* Vg0 = g_V + ((size_t)(bh * S_LEN + lr)) * HD + lcs;

    for (int jt = 0; jt < S_LEN / 64; jt++) {
        const int kb = jt * 64;
        __syncthreads();
        #pragma unroll
        for (int q = 0; q < 4; q++) {
            cvt_store(Kh, Km, lr, lcs + q * 4, *(const float4*)(Kg0 + (size_t)kb * HD + q * 4));
            cvt_store(Vh, Vm, lr, lcs + q * 4, *(const float4*)(Vg0 + (size_t)kb * HD + q * 4));
        }
        __syncthreads();

        // ---- S = Q K^T  (3-term bf16) ----
        float s[8][4];
        #pragma unroll
        for (int i = 0; i < 8; i++)
            #pragma unroll
            for (int j = 0; j < 4; j++) s[i][j] = 0.f;

        #pragma unroll
        for (int ks = 0; ks < 4; ks++) {
            const int colb = ks * 32 + lcolb;
            uint32_t aqh[4], aqm[4], bk[4][4];
            const uint32_t offq = sw_off(wid * 16 + lrow, colb);
            ldsm4(aqh, Qh + offq);
            ldsm4(aqm, Qm + offq);
            #pragma unroll
            for (int nb = 0; nb < 4; nb++)
                ldsm4(bk[nb], Kh + sw_off(nb * 16 + lrow, colb));
            #pragma unroll
            for (int nb = 0; nb < 4; nb++) {
                mma_bf(s[2 * nb],     aqh[0], aqh[1], aqh[2], aqh[3], bk[nb][0], bk[nb][2]);
                mma_bf(s[2 * nb + 1], aqh[0], aqh[1], aqh[2], aqh[3], bk[nb][1], bk[nb][3]);
                mma_bf(s[2 * nb],     aqm[0], aqm[1], aqm[2], aqm[3], bk[nb][0], bk[nb][2]);
                mma_bf(s[2 * nb + 1], aqm[0], aqm[1], aqm[2], aqm[3], bk[nb][1], bk[nb][3]);
            }
            #pragma unroll
            for (int nb = 0; nb < 4; nb++)
                ldsm4(bk[nb], Km + sw_off(nb * 16 + lrow, colb));
            #pragma unroll
            for (int nb = 0; nb < 4; nb++) {
                mma_bf(s[2 * nb],     aqh[0], aqh[1], aqh[2], aqh[3], bk[nb][0], bk[nb][2]);
                mma_bf(s[2 * nb + 1], aqh[0], aqh[1], aqh[2], aqh[3], bk[nb][1], bk[nb][3]);
            }
        }

        // ---- scale + relative-position bias ----
        #pragma unroll
        for (int nf = 0; nf < 8; nf++) {
            const int j = kb + nf * 8 + 2 * t;
            int d0 = j - i0;       d0 = d0 < -WIN ? -WIN : (d0 > WIN ? WIN : d0);
            int d0b = j + 1 - i0;  d0b = d0b < -WIN ? -WIN : (d0b > WIN ? WIN : d0b);
            int d1 = j - i1;       d1 = d1 < -WIN ? -WIN : (d1 > WIN ? WIN : d1);
            int d1b = j + 1 - i1;  d1b = d1b < -WIN ? -WIN : (d1b > WIN ? WIN : d1b);
            s[nf][0] = s[nf][0] * 0.125f + __ldg(rpb0 + d0);
            s[nf][1] = s[nf][1] * 0.125f + __ldg(rpb0 + d0b);
            s[nf][2] = s[nf][2] * 0.125f + __ldg(rpb1 + d1);
            s[nf][3] = s[nf][3] * 0.125f + __ldg(rpb1 + d1b);
        }

        // ---- online softmax (row groups: 4 lanes per row) ----
        float mx0 = -1e30f, mx1 = -1e30f;
        #pragma unroll
        for (int nf = 0; nf < 8; nf++) {
            mx0 = fmaxf(mx0, fmaxf(s[nf][0], s[nf][1]));
            mx1 = fmaxf(mx1, fmaxf(s[nf][2], s[nf][3]));
        }
        mx0 = fmaxf(mx0, __shfl_xor_sync(0xffffffffu, mx0, 1));
        mx0 = fmaxf(mx0, __shfl_xor_sync(0xffffffffu, mx0, 2));
        mx1 = fmaxf(mx1, __shfl_xor_sync(0xffffffffu, mx1, 1));
        mx1 = fmaxf(mx1, __shfl_xor_sync(0xffffffffu, mx1, 2));
        const float mn0 = fmaxf(macc[0], mx0);
        const float mn1 = fmaxf(macc[1], mx1);
        const float cr0 = __expf(macc[0] - mn0);
        const float cr1 = __expf(macc[1] - mn1);
        float sum0 = 0.f, sum1 = 0.f;
        #pragma unroll
        for (int nf = 0; nf < 8; nf++) {
            s[nf][0] = __expf(s[nf][0] - mn0);
            s[nf][1] = __expf(s[nf][1] - mn0);
            s[nf][2] = __expf(s[nf][2] - mn1);
            s[nf][3] = __expf(s[nf][3] - mn1);
            sum0 += s[nf][0] + s[nf][1];
            sum1 += s[nf][2] + s[nf][3];
        }
        sum0 += __shfl_xor_sync(0xffffffffu, sum0, 1);
        sum0 += __shfl_xor_sync(0xffffffffu, sum0, 2);
        sum1 += __shfl_xor_sync(0xffffffffu, sum1, 1);
        sum1 += __shfl_xor_sync(0xffffffffu, sum1, 2);
        lacc[0] = lacc[0] * cr0 + sum0;  macc[0] = mn0;
        lacc[1] = lacc[1] * cr1 + sum1;  macc[1] = mn1;
        #pragma unroll
        for (int nf = 0; nf < 8; nf++) {
            o[nf][0] *= cr0; o[nf][1] *= cr0;
            o[nf][2] *= cr1; o[nf][3] *= cr1;
        }

        // ---- P -> bf16 hi/mid (in registers; C-frag == A-frag layout) ----
        uint32_t p0h[8], p0m[8], p1h[8], p1m[8];
        #pragma unroll
        for (int nf = 0; nf < 8; nf++) {
            p0h[nf] = packbf(s[nf][0], s[nf][1]);
            p0m[nf] = packbf(s[nf][0] - unlo(p0h[nf]), s[nf][1] - unhi(p0h[nf]));
            p1h[nf] = packbf(s[nf][2], s[nf][3]);
            p1m[nf] = packbf(s[nf][2] - unlo(p1h[nf]), s[nf][3] - unhi(p1h[nf]));
        }

        // ---- O += P V  (3-term bf16) ----
        #pragma unroll
        for (int kk = 0; kk < 4; kk++) {
            uint32_t bv[4][4];
            const int rowv = kk * 16 + lrow;
            #pragma unroll
            for (int nb = 0; nb < 4; nb++)
                ldsm4t(bv[nb], Vh + sw_off(rowv, nb * 32 + lcolb));
            const uint32_t a0h = p0h[2 * kk], a1h = p1h[2 * kk];
            const uint32_t a2h = p0h[2 * kk + 1], a3h = p1h[2 * kk + 1];
            const uint32_t a0m = p0m[2 * kk], a1m = p1m[2 * kk];
            const uint32_t a2m = p0m[2 * kk + 1], a3m = p1m[2 * kk + 1];
            #pragma unroll
            for (int nb = 0; nb < 4; nb++) {
                mma_bf(o[2 * nb],     a0h, a1h, a2h, a3h, bv[nb][0], bv[nb][1]);
                mma_bf(o[2 * nb + 1], a0h, a1h, a2h, a3h, bv[nb][2], bv[nb][3]);
                mma_bf(o[2 * nb],     a0m, a1m, a2m, a3m, bv[nb][0], bv[nb][1]);
                mma_bf(o[2 * nb + 1], a0m, a1m, a2m, a3m, bv[nb][2], bv[nb][3]);
            }
            #pragma unroll
            for (int nb = 0; nb < 4; nb++)
                ldsm4t(bv[nb], Vm + sw_off(rowv, nb * 32 + lcolb));
            #pragma unroll
            for (int nb = 0; nb < 4; nb++) {
                mma_bf(o[2 * nb],     a0h, a1h, a2h, a3h, bv[nb][0], bv[nb][1]);
                mma_bf(o[2 * nb + 1], a0h, a1h, a2h, a3h, bv[nb][2], bv[nb][3]);
            }
        }
    }

    // ---- epilogue ----
    const float inv0 = 1.f / lacc[0];
    const float inv1 = 1.f / lacc[1];
    const int bb = bh >> 4, hh = bh & 15;
    #pragma unroll
    for (int nf = 0; nf < 8; nf++) {
        const int ch = hh * HD + nf * 8 + 2 * t;
        *(float2*)&out[((size_t)(bb * S_LEN + i0)) * D_MODEL + ch] =
            make_float2(o[nf][0] * inv0, o[nf][1] * inv0);
        *(float2*)&out[((size_t)(bb * S_LEN + i1)) * D_MODEL + ch] =
            make_float2(o[nf][2] * inv1, o[nf][3] * inv1);
    }
}

// ---------------------------------------------------------------------------
extern "C" void kernel_launch(void* const* d_in, const int* in_sizes, int n_in,
                              void* d_out, int out_size) {
    (void)in_sizes; (void)n_in; (void)out_size;
    const float* x    = (const float*)d_in[0];
    const float* Wqkv = (const float*)d_in[1];
    const float* bqkv = (const float*)d_in[2];
    const float* Wr   = (const float*)d_in[3];
    const float* br   = (const float*)d_in[4];
    float* out = (float*)d_out;

    cudaFuncSetAttribute(qkv_mma_kernel, cudaFuncAttributeMaxDynamicSharedMemorySize,
                         QKV_SMEM_B);
    qkv_mma_kernel<<<768, 256, QKV_SMEM_B>>>(x, Wqkv, bqkv);

    dim3 g2(32, 32);
    rp_kernel<<<g2, 256>>>(Wr, br);

    cudaFuncSetAttribute(attn_mma_kernel, cudaFuncAttributeMaxDynamicSharedMemorySize,
                         ATT_SMEM_B);
    dim3 g3(16, 32);
    attn_mma_kernel<<<g3, 256, ATT_SMEM_B>>>(out);
}

// round 7
// speedup vs baseline: 2.4440x; 1.2192x over previous
#include <cuda_runtime.h>
#include <cuda_bf16.h>
#include <cstdint>

#define HEADS   16
#define S_LEN   2048
#define D_MODEL 1024
#define HD      64
#define BATCH   2
#define BH      (BATCH*HEADS)     // 32
#define R_SZ    257
#define WIN     128

// Scratch (allocation-free rule: device globals)
__device__ float    g_Q [BH * S_LEN * HD];          // fp32 Q for rp kernel
__device__ float    g_RP[BH * S_LEN * R_SZ];        // ~67 MB
__device__ uint32_t g_Xp[4096 * 1024];              // X  split bf16 hi|mid interleaved
__device__ uint32_t g_Wp[3072 * 1024];              // W  split
__device__ uint32_t g_Qh[BH * S_LEN * 32];          // packed bf16x2, 32 u32 per row
__device__ uint32_t g_Qm[BH * S_LEN * 32];
__device__ uint32_t g_Kh[BH * S_LEN * 32];
__device__ uint32_t g_Km[BH * S_LEN * 32];
__device__ uint32_t g_Vh[BH * S_LEN * 32];
__device__ uint32_t g_Vm[BH * S_LEN * 32];

// ===========================================================================
// Helpers
// ===========================================================================
__device__ __forceinline__ uint32_t smem_u32(const void* p) {
    uint32_t a;
    asm("{ .reg .u64 t; cvta.to.shared.u64 t, %1; cvt.u32.u64 %0, t; }"
        : "=r"(a) : "l"(p));
    return a;
}
__device__ __forceinline__ void ldsm4(uint32_t* r, uint32_t a) {
    asm volatile("ldmatrix.sync.aligned.m8n8.x4.shared.b16 {%0,%1,%2,%3}, [%4];"
                 : "=r"(r[0]), "=r"(r[1]), "=r"(r[2]), "=r"(r[3]) : "r"(a));
}
__device__ __forceinline__ void ldsm4t(uint32_t* r, uint32_t a) {
    asm volatile("ldmatrix.sync.aligned.m8n8.x4.trans.shared.b16 {%0,%1,%2,%3}, [%4];"
                 : "=r"(r[0]), "=r"(r[1]), "=r"(r[2]), "=r"(r[3]) : "r"(a));
}
__device__ __forceinline__ void mma_bf(float* c, uint32_t a0, uint32_t a1,
                                       uint32_t a2, uint32_t a3,
                                       uint32_t b0, uint32_t b1) {
    asm volatile("mma.sync.aligned.m16n8k16.row.col.f32.bf16.bf16.f32 "
                 "{%0,%1,%2,%3}, {%4,%5,%6,%7}, {%8,%9}, {%0,%1,%2,%3};"
                 : "+f"(c[0]), "+f"(c[1]), "+f"(c[2]), "+f"(c[3])
                 : "r"(a0), "r"(a1), "r"(a2), "r"(a3), "r"(b0), "r"(b1));
}
__device__ __forceinline__ uint32_t packbf(float lo, float hi) {
    uint32_t r;
    asm("cvt.rn.bf16x2.f32 %0, %1, %2;" : "=r"(r) : "f"(hi), "f"(lo));
    return r;
}
__device__ __forceinline__ float unlo(uint32_t p) { return __uint_as_float(p << 16); }
__device__ __forceinline__ float unhi(uint32_t p) { return __uint_as_float(p & 0xFFFF0000u); }

__device__ __forceinline__ void cpa16(uint32_t dst, const void* src) {
    asm volatile("cp.async.cg.shared.global [%0], [%1], 16;"
                 :: "r"(dst), "l"(src) : "memory");
}
#define CP_COMMIT() asm volatile("cp.async.commit_group;" ::: "memory")
#define CP_WAIT(N)  asm volatile("cp.async.wait_group %0;" :: "n"(N) : "memory")

// 128-byte rows: swizzle = XOR bits[4:6] with (row&7)
__device__ __forceinline__ uint32_t sw_off(int row, int colb) {
    return (uint32_t)row * 128u + (((uint32_t)colb) ^ (((uint32_t)row & 7u) << 4));
}

// ===========================================================================
// Kernel 0: split fp32 matrix [rows x 1024] into interleaved bf16 hi|mid.
// Output row = 1024 u32 (4096 B); k-block kb (32 cols): u32 [kb*32 .. +16) hi,
// [+16 .. +32) mid  -> each k-chunk is one contiguous 128B segment.
// ===========================================================================
__global__ __launch_bounds__(256)
void split_kernel(const float* __restrict__ src, uint32_t* __restrict__ dst, int n4) {
    int i = blockIdx.x * blockDim.x + threadIdx.x;
    if (i >= n4) return;
    int idx = i * 4;
    int row = idx >> 10, col = idx & 1023;
    float4 v = *(const float4*)(src + idx);
    int kb = col >> 5, cw = col & 31;
    int base = row * 1024 + kb * 32 + (cw >> 1);
    uint32_t h0 = packbf(v.x, v.y), h1 = packbf(v.z, v.w);
    uint32_t m0 = packbf(v.x - unlo(h0), v.y - unhi(h0));
    uint32_t m1 = packbf(v.z - unlo(h1), v.w - unhi(h1));
    dst[base]      = h0;  dst[base + 1]      = h1;
    dst[base + 16] = m0;  dst[base + 16 + 1] = m1;
}

// ===========================================================================
// Kernel 1: QKV projection, bf16 3-term mma, cp.async double-buffered.
// CTA 128x128, k-chunk 32. smem stage = A(16K)+B(16K); 2 stages = 64KB.
// ===========================================================================
#define QKV_SMEM_B (2 * 32768)

__global__ __launch_bounds__(256, 2)
void qkv_mma_kernel(const float* __restrict__ bias) {
    extern __shared__ char qsm[];
    const uint32_t base = smem_u32(qsm);

    const int tid = threadIdx.x;
    const int lane = tid & 31, wid = tid >> 5;
    const int wm = wid & 3, wn = wid >> 2;
    const int bx = blockIdx.x % 24, by = blockIdx.x / 24;
    const int m0 = by * 128, n0 = bx * 128;
    const int lrow = lane & 15, lcolb = (lane >> 4) * 16;

    const int cr = tid >> 1;            // copy row 0..127
    const int ch = tid & 1;             // copy half
    const char* Asrc = (const char*)g_Xp + (size_t)(m0 + cr) * 4096 + ch * 64;
    const char* Bsrc = (const char*)g_Wp + (size_t)(n0 + cr) * 4096 + ch * 64;

    float c[16][4];
    #pragma unroll
    for (int i = 0; i < 16; i++)
        #pragma unroll
        for (int j = 0; j < 4; j++) c[i][j] = 0.f;

    auto copy_stage = [&](int kc, uint32_t stg) {
        const uint32_t As = stg, Bs = stg + 16384;
        #pragma unroll
        for (int q = 0; q < 4; q++) {
            const int colb = ch * 64 + q * 16;
            cpa16(As + sw_off(cr, colb), Asrc + (size_t)kc * 128 + q * 16);
            cpa16(Bs + sw_off(cr, colb), Bsrc + (size_t)kc * 128 + q * 16);
        }
    };

    copy_stage(0, base);
    CP_COMMIT();

    for (int kc = 0; kc < 32; kc++) {
        const uint32_t stg = base + (uint32_t)(kc & 1) * 32768;
        if (kc + 1 < 32) {
            copy_stage(kc + 1, base + (uint32_t)((kc + 1) & 1) * 32768);
            CP_COMMIT();
            CP_WAIT(1);
        } else {
            CP_WAIT(0);
        }
        __syncthreads();

        const uint32_t As = stg, Bs = stg + 16384;
        #pragma unroll
        for (int ks = 0; ks < 2; ks++) {
            const int hi_cb = ks * 32 + lcolb;
            const int mi_cb = 64 + ks * 32 + lcolb;
            uint32_t ah[2][4], am[2][4], bb[4][4];
            #pragma unroll
            for (int mf = 0; mf < 2; mf++) {
                const int r = wm * 32 + mf * 16 + lrow;
                ldsm4(ah[mf], As + sw_off(r, hi_cb));
                ldsm4(am[mf], As + sw_off(r, mi_cb));
            }
            #pragma unroll
            for (int nb = 0; nb < 4; nb++)
                ldsm4(bb[nb], Bs + sw_off(wn * 64 + nb * 16 + lrow, hi_cb));
            #pragma unroll
            for (int mf = 0; mf < 2; mf++)
                #pragma unroll
                for (int nb = 0; nb < 4; nb++) {
                    mma_bf(c[mf * 8 + 2 * nb],     ah[mf][0], ah[mf][1], ah[mf][2], ah[mf][3], bb[nb][0], bb[nb][2]);
                    mma_bf(c[mf * 8 + 2 * nb + 1], ah[mf][0], ah[mf][1], ah[mf][2], ah[mf][3], bb[nb][1], bb[nb][3]);
                    mma_bf(c[mf * 8 + 2 * nb],     am[mf][0], am[mf][1], am[mf][2], am[mf][3], bb[nb][0], bb[nb][2]);
                    mma_bf(c[mf * 8 + 2 * nb + 1], am[mf][0], am[mf][1], am[mf][2], am[mf][3], bb[nb][1], bb[nb][3]);
                }
            #pragma unroll
            for (int nb = 0; nb < 4; nb++)
                ldsm4(bb[nb], Bs + sw_off(wn * 64 + nb * 16 + lrow, mi_cb));
            #pragma unroll
            for (int mf = 0; mf < 2; mf++)
                #pragma unroll
                for (int nb = 0; nb < 4; nb++) {
                    mma_bf(c[mf * 8 + 2 * nb],     ah[mf][0], ah[mf][1], ah[mf][2], ah[mf][3], bb[nb][0], bb[nb][2]);
                    mma_bf(c[mf * 8 + 2 * nb + 1], ah[mf][0], ah[mf][1], ah[mf][2], ah[mf][3], bb[nb][1], bb[nb][3]);
                }
        }
        __syncthreads();
    }

    // Epilogue: decode (head, type, channel); store fp32 Q + packed bf16 hi/mid.
    const int g = lane >> 2, t = lane & 3;
    #pragma unroll
    for (int mf = 0; mf < 2; mf++) {
        const int mr0 = m0 + wm * 32 + mf * 16 + g;
        const int bb0 = mr0 >> 11, sp0 = mr0 & 2047;
        const int sp1 = (mr0 + 8) & 2047;
        #pragma unroll
        for (int nf = 0; nf < 8; nf++) {
            const int n = n0 + wn * 64 + nf * 8 + t * 2;
            const float2 bv = *(const float2*)(bias + n);
            const int head = n / 192;
            const int rem  = n - head * 192;
            const int type = rem >> 6;
            const int c64  = rem & 63;
            float* ci = c[mf * 8 + nf];
            const float v0 = ci[0] + bv.x, v1 = ci[1] + bv.y;
            const float v2 = ci[2] + bv.x, v3 = ci[3] + bv.y;
            const int row0 = (bb0 * HEADS + head) * S_LEN + sp0;
            const int row1 = (bb0 * HEADS + head) * S_LEN + sp1;
            const uint32_t h0 = packbf(v0, v1);
            const uint32_t mm0 = packbf(v0 - unlo(h0), v1 - unhi(h0));
            const uint32_t h1 = packbf(v2, v3);
            const uint32_t mm1 = packbf(v2 - unlo(h1), v3 - unhi(h1));
            const size_t p0 = (size_t)row0 * 32 + (c64 >> 1);
            const size_t p1 = (size_t)row1 * 32 + (c64 >> 1);
            if (type == 0) {
                *(float2*)&g_Q[(size_t)row0 * HD + c64] = make_float2(v0, v1);
                *(float2*)&g_Q[(size_t)row1 * HD + c64] = make_float2(v2, v3);
                g_Qh[p0] = h0; g_Qm[p0] = mm0;
                g_Qh[p1] = h1; g_Qm[p1] = mm1;
            } else if (type == 1) {
                g_Kh[p0] = h0; g_Km[p0] = mm0;
                g_Kh[p1] = h1; g_Km[p1] = mm1;
            } else {
                g_Vh[p0] = h0; g_Vm[p0] = mm0;
                g_Vh[p1] = h1; g_Vm[p1] = mm1;
            }
        }
    }
}

// ---------------------------------------------------------------------------
// Kernel 2: rp[bh][i][r] = q[bh][i] . Wr[r] + br[r]   (fp32 FFMA, exact)
// ---------------------------------------------------------------------------
__global__ __launch_bounds__(256)
void rp_kernel(const float* __restrict__ Wr, const float* __restrict__ br) {
    __shared__ float Qs[64 * 64];
    __shared__ float Ws[64 * 65];
    __shared__ float brs[64];

    const int st = blockIdx.x;
    const int bh = blockIdx.y;
    const int tid = threadIdx.x;
    const int tx = tid & 15, ty = tid >> 4;
    const int i0 = ty * 4, r0 = tx * 4;
    const int q_base = st * 64;

    const float* Qg = g_Q + (bh * S_LEN + q_base) * HD;
    #pragma unroll
    for (int l = 0; l < 4; l++) {
        int idx = tid + l * 256;
        int row = idx >> 4;
        int c4  = (idx & 15) * 4;
        *(float4*)&Qs[row * 64 + c4] = *(const float4*)(Qg + row * 64 + c4);
    }

    for (int rt = 0; rt < 5; rt++) {
        const int r_base = rt * 64;
        #pragma unroll
        for (int l = 0; l < 4; l++) {
            int idx = tid + l * 256;
            int row = idx >> 4;
            int c4  = (idx & 15) * 4;
            int r   = r_base + row;
            float4 v = make_float4(0.f, 0.f, 0.f, 0.f);
            if (r < R_SZ) v = *(const float4*)(Wr + r * 64 + c4);
            float* d = &Ws[row * 65 + c4];
            d[0] = v.x; d[1] = v.y; d[2] = v.z; d[3] = v.w;
        }
        if (tid < 64) {
            int r = r_base + tid;
            brs[tid] = (r < R_SZ) ? __ldg(&br[r]) : 0.f;
        }
        __syncthreads();

        float acc[4][4];
        #pragma unroll
        for (int i = 0; i < 4; i++)
            #pragma unroll
            for (int j = 0; j < 4; j++) acc[i][j] = 0.f;

        #pragma unroll 8
        for (int c = 0; c < 64; c++) {
            float a[4], bfr[4];
            #pragma unroll
            for (int i = 0; i < 4; i++) a[i]   = Qs[(i0 + i) * 64 + c];
            #pragma unroll
            for (int j = 0; j < 4; j++) bfr[j] = Ws[(r0 + j) * 65 + c];
            #pragma unroll
            for (int i = 0; i < 4; i++)
                #pragma unroll
                for (int j = 0; j < 4; j++)
                    acc[i][j] = fmaf(a[i], bfr[j], acc[i][j]);
        }

        #pragma unroll
        for (int i = 0; i < 4; i++) {
            const int ig = q_base + i0 + i;
            #pragma unroll
            for (int j = 0; j < 4; j++) {
                const int r = r_base + r0 + j;
                if (r < R_SZ)
                    g_RP[(bh * S_LEN + ig) * R_SZ + r] = acc[i][j] + brs[r0 + j];
            }
        }
        __syncthreads();
    }
}

// ===========================================================================
// Kernel 3: flash attention, preconverted bf16, cp.async double-buffered K/V.
// smem: Qh(16K) Qm(16K) + 2 stages x {Kh,Km,Vh,Vm 8K each} = 96KB.
// ===========================================================================
#define ATT_SMEM_B (32768 + 2 * 32768)

__global__ __launch_bounds__(256, 2)
void attn_mma_kernel(float* __restrict__ out) {
    extern __shared__ char asm_[];
    const uint32_t base = smem_u32(asm_);
    const uint32_t Qh = base, Qm = base + 16384;
    const uint32_t stg0 = base + 32768;

    const int qt = blockIdx.x, bh = blockIdx.y;
    const int q0 = qt * 128;
    const int tid = threadIdx.x;
    const int lane = tid & 31, wid = tid >> 5;
    const int g = lane >> 2, t = lane & 3;
    const int lrow = lane & 15, lcolb = (lane >> 4) * 16;

    // Q copy: 128 rows x 8 chunks x 2 tiles
    {
        const int r = tid >> 1;
        const int j0c = (tid & 1) * 4;
        const size_t rowb = (size_t)(bh * S_LEN + q0 + r) * 128;
        #pragma unroll
        for (int q = 0; q < 4; q++) {
            cpa16(Qh + sw_off(r, (j0c + q) * 16), (const char*)g_Qh + rowb + (j0c + q) * 16);
            cpa16(Qm + sw_off(r, (j0c + q) * 16), (const char*)g_Qm + rowb + (j0c + q) * 16);
        }
    }

    const int kvr = tid >> 2;              // 0..63
    const int kvj = (tid & 3) * 2;         // chunk pair
    auto copy_kv = [&](int kb, uint32_t stg) {
        const size_t rowb = (size_t)(bh * S_LEN + kb + kvr) * 128;
        const uint32_t Ksh = stg, Ksm = stg + 8192, Vsh = stg + 16384, Vsm = stg + 24576;
        #pragma unroll
        for (int q = 0; q < 2; q++) {
            const int cb = (kvj + q) * 16;
            const uint32_t so = sw_off(kvr, cb);
            cpa16(Ksh + so, (const char*)g_Kh + rowb + cb);
            cpa16(Ksm + so, (const char*)g_Km + rowb + cb);
            cpa16(Vsh + so, (const char*)g_Vh + rowb + cb);
            cpa16(Vsm + so, (const char*)g_Vm + rowb + cb);
        }
    };

    copy_kv(0, stg0);
    CP_COMMIT();

    float o[8][4];
    #pragma unroll
    for (int i = 0; i < 8; i++)
        #pragma unroll
        for (int j = 0; j < 4; j++) o[i][j] = 0.f;
    float macc[2] = {-1e30f, -1e30f};
    float lacc[2] = {0.f, 0.f};

    const int i0 = q0 + wid * 16 + g;
    const int i1 = i0 + 8;
    const float* rpb0 = g_RP + ((size_t)(bh * S_LEN + i0)) * R_SZ + WIN;
    const float* rpb1 = g_RP + ((size_t)(bh * S_LEN + i1)) * R_SZ + WIN;

    for (int jt = 0; jt < S_LEN / 64; jt++) {
        const int kb = jt * 64;
        const uint32_t stg = stg0 + (uint32_t)(jt & 1) * 32768;
        if (jt + 1 < S_LEN / 64) {
            copy_kv(kb + 64, stg0 + (uint32_t)((jt + 1) & 1) * 32768);
            CP_COMMIT();
            CP_WAIT(1);
        } else {
            CP_WAIT(0);
        }
        __syncthreads();

        const uint32_t Ksh = stg, Ksm = stg + 8192, Vsh = stg + 16384, Vsm = stg + 24576;

        // ---- S = Q K^T  (Qh*Kh + Qm*Kh + Qh*Km) ----
        float s[8][4];
        #pragma unroll
        for (int i = 0; i < 8; i++)
            #pragma unroll
            for (int j = 0; j < 4; j++) s[i][j] = 0.f;

        #pragma unroll
        for (int ks = 0; ks < 4; ks++) {
            const int colb = ks * 32 + lcolb;
            uint32_t aqh[4], aqm[4], bk[4][4];
            const uint32_t offq = sw_off(wid * 16 + lrow, colb);
            ldsm4(aqh, Qh + offq);
            ldsm4(aqm, Qm + offq);
            #pragma unroll
            for (int nb = 0; nb < 4; nb++)
                ldsm4(bk[nb], Ksh + sw_off(nb * 16 + lrow, colb));
            #pragma unroll
            for (int nb = 0; nb < 4; nb++) {
                mma_bf(s[2 * nb],     aqh[0], aqh[1], aqh[2], aqh[3], bk[nb][0], bk[nb][2]);
                mma_bf(s[2 * nb + 1], aqh[0], aqh[1], aqh[2], aqh[3], bk[nb][1], bk[nb][3]);
                mma_bf(s[2 * nb],     aqm[0], aqm[1], aqm[2], aqm[3], bk[nb][0], bk[nb][2]);
                mma_bf(s[2 * nb + 1], aqm[0], aqm[1], aqm[2], aqm[3], bk[nb][1], bk[nb][3]);
            }
            #pragma unroll
            for (int nb = 0; nb < 4; nb++)
                ldsm4(bk[nb], Ksm + sw_off(nb * 16 + lrow, colb));
            #pragma unroll
            for (int nb = 0; nb < 4; nb++) {
                mma_bf(s[2 * nb],     aqh[0], aqh[1], aqh[2], aqh[3], bk[nb][0], bk[nb][2]);
                mma_bf(s[2 * nb + 1], aqh[0], aqh[1], aqh[2], aqh[3], bk[nb][1], bk[nb][3]);
            }
        }

        // ---- scale + relative-position bias ----
        #pragma unroll
        for (int nf = 0; nf < 8; nf++) {
            const int j = kb + nf * 8 + 2 * t;
            int d0 = j - i0;       d0 = d0 < -WIN ? -WIN : (d0 > WIN ? WIN : d0);
            int d0b = j + 1 - i0;  d0b = d0b < -WIN ? -WIN : (d0b > WIN ? WIN : d0b);
            int d1 = j - i1;       d1 = d1 < -WIN ? -WIN : (d1 > WIN ? WIN : d1);
            int d1b = j + 1 - i1;  d1b = d1b < -WIN ? -WIN : (d1b > WIN ? WIN : d1b);
            s[nf][0] = s[nf][0] * 0.125f + __ldg(rpb0 + d0);
            s[nf][1] = s[nf][1] * 0.125f + __ldg(rpb0 + d0b);
            s[nf][2] = s[nf][2] * 0.125f + __ldg(rpb1 + d1);
            s[nf][3] = s[nf][3] * 0.125f + __ldg(rpb1 + d1b);
        }

        // ---- online softmax ----
        float mx0 = -1e30f, mx1 = -1e30f;
        #pragma unroll
        for (int nf = 0; nf < 8; nf++) {
            mx0 = fmaxf(mx0, fmaxf(s[nf][0], s[nf][1]));
            mx1 = fmaxf(mx1, fmaxf(s[nf][2], s[nf][3]));
        }
        mx0 = fmaxf(mx0, __shfl_xor_sync(0xffffffffu, mx0, 1));
        mx0 = fmaxf(mx0, __shfl_xor_sync(0xffffffffu, mx0, 2));
        mx1 = fmaxf(mx1, __shfl_xor_sync(0xffffffffu, mx1, 1));
        mx1 = fmaxf(mx1, __shfl_xor_sync(0xffffffffu, mx1, 2));
        const float mn0 = fmaxf(macc[0], mx0);
        const float mn1 = fmaxf(macc[1], mx1);
        const float cr0 = __expf(macc[0] - mn0);
        const float cr1 = __expf(macc[1] - mn1);
        float sum0 = 0.f, sum1 = 0.f;
        #pragma unroll
        for (int nf = 0; nf < 8; nf++) {
            s[nf][0] = __expf(s[nf][0] - mn0);
            s[nf][1] = __expf(s[nf][1] - mn0);
            s[nf][2] = __expf(s[nf][2] - mn1);
            s[nf][3] = __expf(s[nf][3] - mn1);
            sum0 += s[nf][0] + s[nf][1];
            sum1 += s[nf][2] + s[nf][3];
        }
        sum0 += __shfl_xor_sync(0xffffffffu, sum0, 1);
        sum0 += __shfl_xor_sync(0xffffffffu, sum0, 2);
        sum1 += __shfl_xor_sync(0xffffffffu, sum1, 1);
        sum1 += __shfl_xor_sync(0xffffffffu, sum1, 2);
        lacc[0] = lacc[0] * cr0 + sum0;  macc[0] = mn0;
        lacc[1] = lacc[1] * cr1 + sum1;  macc[1] = mn1;
        #pragma unroll
        for (int nf = 0; nf < 8; nf++) {
            o[nf][0] *= cr0; o[nf][1] *= cr0;
            o[nf][2] *= cr1; o[nf][3] *= cr1;
        }

        // ---- P -> bf16 hi/mid in registers ----
        uint32_t p0h[8], p0m[8], p1h[8], p1m[8];
        #pragma unroll
        for (int nf = 0; nf < 8; nf++) {
            p0h[nf] = packbf(s[nf][0], s[nf][1]);
            p0m[nf] = packbf(s[nf][0] - unlo(p0h[nf]), s[nf][1] - unhi(p0h[nf]));
            p1h[nf] = packbf(s[nf][2], s[nf][3]);
            p1m[nf] = packbf(s[nf][2] - unlo(p1h[nf]), s[nf][3] - unhi(p1h[nf]));
        }

        // ---- O += P V ----
        #pragma unroll
        for (int kk = 0; kk < 4; kk++) {
            uint32_t bv[4][4];
            const int rowv = kk * 16 + lrow;
            #pragma unroll
            for (int nb = 0; nb < 4; nb++)
                ldsm4t(bv[nb], Vsh + sw_off(rowv, nb * 32 + lcolb));
            const uint32_t a0h = p0h[2 * kk], a1h = p1h[2 * kk];
            const uint32_t a2h = p0h[2 * kk + 1], a3h = p1h[2 * kk + 1];
            const uint32_t a0m = p0m[2 * kk], a1m = p1m[2 * kk];
            const uint32_t a2m = p0m[2 * kk + 1], a3m = p1m[2 * kk + 1];
            #pragma unroll
            for (int nb = 0; nb < 4; nb++) {
                mma_bf(o[2 * nb],     a0h, a1h, a2h, a3h, bv[nb][0], bv[nb][1]);
                mma_bf(o[2 * nb + 1], a0h, a1h, a2h, a3h, bv[nb][2], bv[nb][3]);
                mma_bf(o[2 * nb],     a0m, a1m, a2m, a3m, bv[nb][0], bv[nb][1]);
                mma_bf(o[2 * nb + 1], a0m, a1m, a2m, a3m, bv[nb][2], bv[nb][3]);
            }
            #pragma unroll
            for (int nb = 0; nb < 4; nb++)
                ldsm4t(bv[nb], Vsm + sw_off(rowv, nb * 32 + lcolb));
            #pragma unroll
            for (int nb = 0; nb < 4; nb++) {
                mma_bf(o[2 * nb],     a0h, a1h, a2h, a3h, bv[nb][0], bv[nb][1]);
                mma_bf(o[2 * nb + 1], a0h, a1h, a2h, a3h, bv[nb][2], bv[nb][3]);
            }
        }
        __syncthreads();
    }

    // ---- epilogue ----
    const float inv0 = 1.f / lacc[0];
    const float inv1 = 1.f / lacc[1];
    const int bb = bh >> 4, hh = bh & 15;
    #pragma unroll
    for (int nf = 0; nf < 8; nf++) {
        const int ch = hh * HD + nf * 8 + 2 * t;
        *(float2*)&out[((size_t)(bb * S_LEN + i0)) * D_MODEL + ch] =
            make_float2(o[nf][0] * inv0, o[nf][1] * inv0);
        *(float2*)&out[((size_t)(bb * S_LEN + i1)) * D_MODEL + ch] =
            make_float2(o[nf][2] * inv1, o[nf][3] * inv1);
    }
}

// ---------------------------------------------------------------------------
extern "C" void kernel_launch(void* const* d_in, const int* in_sizes, int n_in,
                              void* d_out, int out_size) {
    (void)in_sizes; (void)n_in; (void)out_size;
    const float* x    = (const float*)d_in[0];
    const float* Wqkv = (const float*)d_in[1];
    const float* bqkv = (const float*)d_in[2];
    const float* Wr   = (const float*)d_in[3];
    const float* br   = (const float*)d_in[4];
    float* out = (float*)d_out;

    uint32_t* xp; cudaGetSymbolAddress((void**)&xp, g_Xp);
    uint32_t* wp; cudaGetSymbolAddress((void**)&wp, g_Wp);
    split_kernel<<<(4096 * 1024 / 4 + 255) / 256, 256>>>(x, xp, 4096 * 1024 / 4);
    split_kernel<<<(3072 * 1024 / 4 + 255) / 256, 256>>>(Wqkv, wp, 3072 * 1024 / 4);

    cudaFuncSetAttribute(qkv_mma_kernel, cudaFuncAttributeMaxDynamicSharedMemorySize,
                         QKV_SMEM_B);
    qkv_mma_kernel<<<768, 256, QKV_SMEM_B>>>(bqkv);

    dim3 g2(32, 32);
    rp_kernel<<<g2, 256>>>(Wr, br);

    cudaFuncSetAttribute(attn_mma_kernel, cudaFuncAttributeMaxDynamicSharedMemorySize,
                         ATT_SMEM_B);
    dim3 g3(16, 32);
    attn_mma_kernel<<<g3, 256, ATT_SMEM_B>>>(out);
}

// round 10
// speedup vs baseline: 2.7099x; 1.1088x over previous
#include <cuda_runtime.h>
#include <cuda_bf16.h>
#include <cstdint>

#define HEADS   16
#define S_LEN   2048
#define D_MODEL 1024
#define HD      64
#define BATCH   2
#define BH      (BATCH*HEADS)     // 32
#define R_SZ    257
#define WIN     128

// Scratch (allocation-free rule: device globals)
__device__ float    g_Q [BH * S_LEN * HD];          // fp32 Q (rp col-256 path)
__device__ float    g_RP[BH * S_LEN * R_SZ];        // ~67 MB
__device__ uint32_t g_Xp[4096 * 1024];              // X  split bf16 hi|mid interleaved
__device__ uint32_t g_Wp[3072 * 1024];              // W  split
__device__ uint32_t g_Qh[BH * S_LEN * 32];          // packed bf16x2, 32 u32 per row
__device__ uint32_t g_Qm[BH * S_LEN * 32];
__device__ uint32_t g_Kh[BH * S_LEN * 32];
__device__ uint32_t g_Km[BH * S_LEN * 32];
__device__ uint32_t g_Vh[BH * S_LEN * 32];
__device__ uint32_t g_Vm[BH * S_LEN * 32];
__device__ uint32_t g_Wrh[256 * 32];                // Wr rows 0..255 split
__device__ uint32_t g_Wrm[256 * 32];

// ===========================================================================
// Helpers
// ===========================================================================
__device__ __forceinline__ uint32_t smem_u32(const void* p) {
    uint32_t a;
    asm("{ .reg .u64 t; cvta.to.shared.u64 t, %1; cvt.u32.u64 %0, t; }"
        : "=r"(a) : "l"(p));
    return a;
}
__device__ __forceinline__ void ldsm4(uint32_t* r, uint32_t a) {
    asm volatile("ldmatrix.sync.aligned.m8n8.x4.shared.b16 {%0,%1,%2,%3}, [%4];"
                 : "=r"(r[0]), "=r"(r[1]), "=r"(r[2]), "=r"(r[3]) : "r"(a));
}
__device__ __forceinline__ void ldsm4t(uint32_t* r, uint32_t a) {
    asm volatile("ldmatrix.sync.aligned.m8n8.x4.trans.shared.b16 {%0,%1,%2,%3}, [%4];"
                 : "=r"(r[0]), "=r"(r[1]), "=r"(r[2]), "=r"(r[3]) : "r"(a));
}
__device__ __forceinline__ void mma_bf(float* c, uint32_t a0, uint32_t a1,
                                       uint32_t a2, uint32_t a3,
                                       uint32_t b0, uint32_t b1) {
    asm volatile("mma.sync.aligned.m16n8k16.row.col.f32.bf16.bf16.f32 "
                 "{%0,%1,%2,%3}, {%4,%5,%6,%7}, {%8,%9}, {%0,%1,%2,%3};"
                 : "+f"(c[0]), "+f"(c[1]), "+f"(c[2]), "+f"(c[3])
                 : "r"(a0), "r"(a1), "r"(a2), "r"(a3), "r"(b0), "r"(b1));
}
__device__ __forceinline__ uint32_t packbf(float lo, float hi) {
    uint32_t r;
    asm("cvt.rn.bf16x2.f32 %0, %1, %2;" : "=r"(r) : "f"(hi), "f"(lo));
    return r;
}
__device__ __forceinline__ float unlo(uint32_t p) { return __uint_as_float(p << 16); }
__device__ __forceinline__ float unhi(uint32_t p) { return __uint_as_float(p & 0xFFFF0000u); }

__device__ __forceinline__ void cpa16(uint32_t dst, const void* src) {
    asm volatile("cp.async.cg.shared.global [%0], [%1], 16;"
                 :: "r"(dst), "l"(src) : "memory");
}
#define CP_COMMIT() asm volatile("cp.async.commit_group;" ::: "memory")
#define CP_WAIT(N)  asm volatile("cp.async.wait_group %0;" :: "n"(N) : "memory")

// 128-byte rows: swizzle = XOR bits[4:6] with (row&7)
__device__ __forceinline__ uint32_t sw_off(int row, int colb) {
    return (uint32_t)row * 128u + (((uint32_t)colb) ^ (((uint32_t)row & 7u) << 4));
}

// ===========================================================================
// Kernel 0a: split fp32 [rows x 1024] into interleaved bf16 hi|mid.
// ===========================================================================
__global__ __launch_bounds__(256)
void split_kernel(const float* __restrict__ src, uint32_t* __restrict__ dst, int n4) {
    int i = blockIdx.x * blockDim.x + threadIdx.x;
    if (i >= n4) return;
    int idx = i * 4;
    int row = idx >> 10, col = idx & 1023;
    float4 v = *(const float4*)(src + idx);
    int kb = col >> 5, cw = col & 31;
    int base = row * 1024 + kb * 32 + (cw >> 1);
    uint32_t h0 = packbf(v.x, v.y), h1 = packbf(v.z, v.w);
    uint32_t m0 = packbf(v.x - unlo(h0), v.y - unhi(h0));
    uint32_t m1 = packbf(v.z - unlo(h1), v.w - unhi(h1));
    dst[base]      = h0;  dst[base + 1]      = h1;
    dst[base + 16] = m0;  dst[base + 16 + 1] = m1;
}

// Kernel 0b: split Wr rows 0..255 into g_Wrh/g_Wrm (32 u32 per row).
__global__ __launch_bounds__(256)
void wr_split_kernel(const float* __restrict__ Wr) {
    int i = blockIdx.x * blockDim.x + threadIdx.x;   // u32 index
    if (i >= 256 * 32) return;
    int row = i >> 5, cp = i & 31;
    float2 v = *(const float2*)(Wr + row * 64 + cp * 2);
    uint32_t h = packbf(v.x, v.y);
    uint32_t m = packbf(v.x - unlo(h), v.y - unhi(h));
    g_Wrh[i] = h; g_Wrm[i] = m;
}

// ===========================================================================
// Kernel 1: QKV projection, bf16 3-term mma, cp.async double-buffered.
// ===========================================================================
#define QKV_SMEM_B (2 * 32768)

__global__ __launch_bounds__(256, 2)
void qkv_mma_kernel(const float* __restrict__ bias) {
    extern __shared__ char qsm[];
    const uint32_t base = smem_u32(qsm);

    const int tid = threadIdx.x;
    const int lane = tid & 31, wid = tid >> 5;
    const int wm = wid & 3, wn = wid >> 2;
    const int bx = blockIdx.x % 24, by = blockIdx.x / 24;
    const int m0 = by * 128, n0 = bx * 128;
    const int lrow = lane & 15, lcolb = (lane >> 4) * 16;

    const int cr = tid >> 1;
    const int ch = tid & 1;
    const char* Asrc = (const char*)g_Xp + (size_t)(m0 + cr) * 4096 + ch * 64;
    const char* Bsrc = (const char*)g_Wp + (size_t)(n0 + cr) * 4096 + ch * 64;

    float c[16][4];
    #pragma unroll
    for (int i = 0; i < 16; i++)
        #pragma unroll
        for (int j = 0; j < 4; j++) c[i][j] = 0.f;

    auto copy_stage = [&](int kc, uint32_t stg) {
        const uint32_t As = stg, Bs = stg + 16384;
        #pragma unroll
        for (int q = 0; q < 4; q++) {
            const int colb = ch * 64 + q * 16;
            cpa16(As + sw_off(cr, colb), Asrc + (size_t)kc * 128 + q * 16);
            cpa16(Bs + sw_off(cr, colb), Bsrc + (size_t)kc * 128 + q * 16);
        }
    };

    copy_stage(0, base);
    CP_COMMIT();

    for (int kc = 0; kc < 32; kc++) {
        const uint32_t stg = base + (uint32_t)(kc & 1) * 32768;
        if (kc + 1 < 32) {
            copy_stage(kc + 1, base + (uint32_t)((kc + 1) & 1) * 32768);
            CP_COMMIT();
            CP_WAIT(1);
        } else {
            CP_WAIT(0);
        }
        __syncthreads();

        const uint32_t As = stg, Bs = stg + 16384;
        #pragma unroll
        for (int ks = 0; ks < 2; ks++) {
            const int hi_cb = ks * 32 + lcolb;
            const int mi_cb = 64 + ks * 32 + lcolb;
            uint32_t ah[2][4], am[2][4], bb[4][4];
            #pragma unroll
            for (int mf = 0; mf < 2; mf++) {
                const int r = wm * 32 + mf * 16 + lrow;
                ldsm4(ah[mf], As + sw_off(r, hi_cb));
                ldsm4(am[mf], As + sw_off(r, mi_cb));
            }
            #pragma unroll
            for (int nb = 0; nb < 4; nb++)
                ldsm4(bb[nb], Bs + sw_off(wn * 64 + nb * 16 + lrow, hi_cb));
            #pragma unroll
            for (int mf = 0; mf < 2; mf++)
                #pragma unroll
                for (int nb = 0; nb < 4; nb++) {
                    mma_bf(c[mf * 8 + 2 * nb],     ah[mf][0], ah[mf][1], ah[mf][2], ah[mf][3], bb[nb][0], bb[nb][2]);
                    mma_bf(c[mf * 8 + 2 * nb + 1], ah[mf][0], ah[mf][1], ah[mf][2], ah[mf][3], bb[nb][1], bb[nb][3]);
                    mma_bf(c[mf * 8 + 2 * nb],     am[mf][0], am[mf][1], am[mf][2], am[mf][3], bb[nb][0], bb[nb][2]);
                    mma_bf(c[mf * 8 + 2 * nb + 1], am[mf][0], am[mf][1], am[mf][2], am[mf][3], bb[nb][1], bb[nb][3]);
                }
            #pragma unroll
            for (int nb = 0; nb < 4; nb++)
                ldsm4(bb[nb], Bs + sw_off(wn * 64 + nb * 16 + lrow, mi_cb));
            #pragma unroll
            for (int mf = 0; mf < 2; mf++)
                #pragma unroll
                for (int nb = 0; nb < 4; nb++) {
                    mma_bf(c[mf * 8 + 2 * nb],     ah[mf][0], ah[mf][1], ah[mf][2], ah[mf][3], bb[nb][0], bb[nb][2]);
                    mma_bf(c[mf * 8 + 2 * nb + 1], ah[mf][0], ah[mf][1], ah[mf][2], ah[mf][3], bb[nb][1], bb[nb][3]);
                }
        }
        __syncthreads();
    }

    const int g = lane >> 2, t = lane & 3;
    #pragma unroll
    for (int mf = 0; mf < 2; mf++) {
        const int mr0 = m0 + wm * 32 + mf * 16 + g;
        const int bb0 = mr0 >> 11, sp0 = mr0 & 2047;
        const int sp1 = (mr0 + 8) & 2047;
        #pragma unroll
        for (int nf = 0; nf < 8; nf++) {
            const int n = n0 + wn * 64 + nf * 8 + t * 2;
            const float2 bv = *(const float2*)(bias + n);
            const int head = n / 192;
            const int rem  = n - head * 192;
            const int type = rem >> 6;
            const int c64  = rem & 63;
            float* ci = c[mf * 8 + nf];
            const float v0 = ci[0] + bv.x, v1 = ci[1] + bv.y;
            const float v2 = ci[2] + bv.x, v3 = ci[3] + bv.y;
            const int row0 = (bb0 * HEADS + head) * S_LEN + sp0;
            const int row1 = (bb0 * HEADS + head) * S_LEN + sp1;
            const uint32_t h0 = packbf(v0, v1);
            const uint32_t mm0 = packbf(v0 - unlo(h0), v1 - unhi(h0));
            const uint32_t h1 = packbf(v2, v3);
            const uint32_t mm1 = packbf(v2 - unlo(h1), v3 - unhi(h1));
            const size_t p0 = (size_t)row0 * 32 + (c64 >> 1);
            const size_t p1 = (size_t)row1 * 32 + (c64 >> 1);
            if (type == 0) {
                *(float2*)&g_Q[(size_t)row0 * HD + c64] = make_float2(v0, v1);
                *(float2*)&g_Q[(size_t)row1 * HD + c64] = make_float2(v2, v3);
                g_Qh[p0] = h0; g_Qm[p0] = mm0;
                g_Qh[p1] = h1; g_Qm[p1] = mm1;
            } else if (type == 1) {
                g_Kh[p0] = h0; g_Km[p0] = mm0;
                g_Kh[p1] = h1; g_Km[p1] = mm1;
            } else {
                g_Vh[p0] = h0; g_Vm[p0] = mm0;
                g_Vh[p1] = h1; g_Vm[p1] = mm1;
            }
        }
    }
}

// ===========================================================================
// Kernel 2: rp on tensor cores. rp[bh][i][r] = q . Wr[r] + br[r].
// CTA = 128 rows x 128 cols (nhalf selects col half), K=64 single pass.
// Col 256 computed fp32 by threads 0..127 of nhalf==0 CTAs.
// ===========================================================================
#define RP_SMEM_B (4 * 16384)   // Qh, Qm, Wh, Wm

__global__ __launch_bounds__(256, 2)
void rp_mma_kernel(const float* __restrict__ Wr, const float* __restrict__ br) {
    extern __shared__ char rsm[];
    const uint32_t base = smem_u32(rsm);
    const uint32_t Qh = base, Qm = base + 16384;
    const uint32_t Wh = base + 32768, Wm = base + 49152;
    __shared__ float w256[64];

    const int bx = blockIdx.x;           // 0..31: stile*2 + nhalf
    const int bh = blockIdx.y;
    const int stile = bx >> 1, nhalf = bx & 1;
    const int q0 = stile * 128, ncol0 = nhalf * 128;

    const int tid = threadIdx.x;
    const int lane = tid & 31, wid = tid >> 5;
    const int wm = wid & 3, wn = wid >> 2;
    const int lrow = lane & 15, lcolb = (lane >> 4) * 16;

    // async copies: Q tile rows q0..q0+127, Wr rows ncol0..ncol0+127
    {
        const int r = tid >> 1;
        const int j0c = (tid & 1) * 4;
        const size_t qrowb = (size_t)(bh * S_LEN + q0 + r) * 128;
        const size_t wrowb = (size_t)(ncol0 + r) * 128;
        #pragma unroll
        for (int q = 0; q < 4; q++) {
            const int cb = (j0c + q) * 16;
            const uint32_t so = sw_off(r, cb);
            cpa16(Qh + so, (const char*)g_Qh + qrowb + cb);
            cpa16(Qm + so, (const char*)g_Qm + qrowb + cb);
            cpa16(Wh + so, (const char*)g_Wrh + wrowb + cb);
            cpa16(Wm + so, (const char*)g_Wrm + wrowb + cb);
        }
    }
    if (tid < 64) w256[tid] = __ldg(Wr + 256 * 64 + tid);
    CP_COMMIT();
    CP_WAIT(0);
    __syncthreads();

    float c[2][8][4];
    #pragma unroll
    for (int mf = 0; mf < 2; mf++)
        #pragma unroll
        for (int nf = 0; nf < 8; nf++)
            #pragma unroll
            for (int j = 0; j < 4; j++) c[mf][nf][j] = 0.f;

    #pragma unroll
    for (int ks = 0; ks < 4; ks++) {
        const int colb = ks * 32 + lcolb;
        uint32_t ah[2][4], am[2][4], bb[4][4];
        #pragma unroll
        for (int mf = 0; mf < 2; mf++) {
            const int r = wm * 32 + mf * 16 + lrow;
            ldsm4(ah[mf], Qh + sw_off(r, colb));
            ldsm4(am[mf], Qm + sw_off(r, colb));
        }
        #pragma unroll
        for (int nb = 0; nb < 4; nb++)
            ldsm4(bb[nb], Wh + sw_off(wn * 64 + nb * 16 + lrow, colb));
        #pragma unroll
        for (int mf = 0; mf < 2; mf++)
            #pragma unroll
            for (int nb = 0; nb < 4; nb++) {
                mma_bf(c[mf][2 * nb],     ah[mf][0], ah[mf][1], ah[mf][2], ah[mf][3], bb[nb][0], bb[nb][2]);
                mma_bf(c[mf][2 * nb + 1], ah[mf][0], ah[mf][1], ah[mf][2], ah[mf][3], bb[nb][1], bb[nb][3]);
                mma_bf(c[mf][2 * nb],     am[mf][0], am[mf][1], am[mf][2], am[mf][3], bb[nb][0], bb[nb][2]);
                mma_bf(c[mf][2 * nb + 1], am[mf][0], am[mf][1], am[mf][2], am[mf][3], bb[nb][1], bb[nb][3]);
            }
        #pragma unroll
        for (int nb = 0; nb < 4; nb++)
            ldsm4(bb[nb], Wm + sw_off(wn * 64 + nb * 16 + lrow, colb));
        #pragma unroll
        for (int mf = 0; mf < 2; mf++)
            #pragma unroll
            for (int nb = 0; nb < 4; nb++) {
                mma_bf(c[mf][2 * nb],     ah[mf][0], ah[mf][1], ah[mf][2], ah[mf][3], bb[nb][0], bb[nb][2]);
                mma_bf(c[mf][2 * nb + 1], ah[mf][0], ah[mf][1], ah[mf][2], ah[mf][3], bb[nb][1], bb[nb][3]);
            }
    }

    // epilogue: rp cols [ncol0, ncol0+128)
    const int g = lane >> 2, t = lane & 3;
    #pragma unroll
    for (int mf = 0; mf < 2; mf++) {
        const int r0g = q0 + wm * 32 + mf * 16 + g;
        const size_t rb0 = (size_t)(bh * S_LEN + r0g) * R_SZ;
        const size_t rb1 = (size_t)(bh * S_LEN + r0g + 8) * R_SZ;
        #pragma unroll
        for (int nf = 0; nf < 8; nf++) {
            const int col = ncol0 + wn * 64 + nf * 8 + t * 2;
            const float2 bv = *(const float2*)(br + col);
            g_RP[rb0 + col]     = c[mf][nf][0] + bv.x;
            g_RP[rb0 + col + 1] = c[mf][nf][1] + bv.y;
            g_RP[rb1 + col]     = c[mf][nf][2] + bv.x;
            g_RP[rb1 + col + 1] = c[mf][nf][3] + bv.y;
        }
    }

    // col 256 (exact fp32)
    if (nhalf == 0 && tid < 128) {
        const float* qrow = g_Q + (size_t)(bh * S_LEN + q0 + tid) * HD;
        float acc = 0.f;
        #pragma unroll
        for (int k = 0; k < 64; k += 4) {
            float4 qv = *(const float4*)(qrow + k);
            acc += qv.x * w256[k] + qv.y * w256[k + 1]
                 + qv.z * w256[k + 2] + qv.w * w256[k + 3];
        }
        g_RP[(size_t)(bh * S_LEN + q0 + tid) * R_SZ + 256] = acc + __ldg(br + 256);
    }
}

// ===========================================================================
// Kernel 3: flash attention, preconverted bf16, cp.async double-buffered K/V,
// clamped-tile bias fast path.
// ===========================================================================
#define ATT_SMEM_B (32768 + 2 * 32768)

__global__ __launch_bounds__(256, 2)
void attn_mma_kernel(float* __restrict__ out) {
    extern __shared__ char asm_[];
    const uint32_t base = smem_u32(asm_);
    const uint32_t Qh = base, Qm = base + 16384;
    const uint32_t stg0 = base + 32768;

    const int qt = blockIdx.x, bh = blockIdx.y;
    const int q0 = qt * 128;
    const int tid = threadIdx.x;
    const int lane = tid & 31, wid = tid >> 5;
    const int g = lane >> 2, t = lane & 3;
    const int lrow = lane & 15, lcolb = (lane >> 4) * 16;

    {
        const int r = tid >> 1;
        const int j0c = (tid & 1) * 4;
        const size_t rowb = (size_t)(bh * S_LEN + q0 + r) * 128;
        #pragma unroll
        for (int q = 0; q < 4; q++) {
            cpa16(Qh + sw_off(r, (j0c + q) * 16), (const char*)g_Qh + rowb + (j0c + q) * 16);
            cpa16(Qm + sw_off(r, (j0c + q) * 16), (const char*)g_Qm + rowb + (j0c + q) * 16);
        }
    }

    const int kvr = tid >> 2;
    const int kvj = (tid & 3) * 2;
    auto copy_kv = [&](int kb, uint32_t stg) {
        const size_t rowb = (size_t)(bh * S_LEN + kb + kvr) * 128;
        const uint32_t Ksh = stg, Ksm = stg + 8192, Vsh = stg + 16384, Vsm = stg + 24576;
        #pragma unroll
        for (int q = 0; q < 2; q++) {
            const int cb = (kvj + q) * 16;
            const uint32_t so = sw_off(kvr, cb);
            cpa16(Ksh + so, (const char*)g_Kh + rowb + cb);
            cpa16(Ksm + so, (const char*)g_Km + rowb + cb);
            cpa16(Vsh + so, (const char*)g_Vh + rowb + cb);
            cpa16(Vsm + so, (const char*)g_Vm + rowb + cb);
        }
    };

    copy_kv(0, stg0);
    CP_COMMIT();

    float o[8][4];
    #pragma unroll
    for (int i = 0; i < 8; i++)
        #pragma unroll
        for (int j = 0; j < 4; j++) o[i][j] = 0.f;
    float macc[2] = {-1e30f, -1e30f};
    float lacc[2] = {0.f, 0.f};

    const int i0 = q0 + wid * 16 + g;
    const int i1 = i0 + 8;
    const float* rpb0 = g_RP + ((size_t)(bh * S_LEN + i0)) * R_SZ + WIN;
    const float* rpb1 = g_RP + ((size_t)(bh * S_LEN + i1)) * R_SZ + WIN;
    const float rLo0 = __ldg(rpb0 - WIN), rHi0 = __ldg(rpb0 + WIN);
    const float rLo1 = __ldg(rpb1 - WIN), rHi1 = __ldg(rpb1 + WIN);

    for (int jt = 0; jt < S_LEN / 64; jt++) {
        const int kb = jt * 64;
        const uint32_t stg = stg0 + (uint32_t)(jt & 1) * 32768;
        if (jt + 1 < S_LEN / 64) {
            copy_kv(kb + 64, stg0 + (uint32_t)((jt + 1) & 1) * 32768);
            CP_COMMIT();
            CP_WAIT(1);
        } else {
            CP_WAIT(0);
        }
        __syncthreads();

        const uint32_t Ksh = stg, Ksm = stg + 8192, Vsh = stg + 16384, Vsm = stg + 24576;

        float s[8][4];
        #pragma unroll
        for (int i = 0; i < 8; i++)
            #pragma unroll
            for (int j = 0; j < 4; j++) s[i][j] = 0.f;

        #pragma unroll
        for (int ks = 0; ks < 4; ks++) {
            const int colb = ks * 32 + lcolb;
            uint32_t aqh[4], aqm[4], bk[4][4];
            const uint32_t offq = sw_off(wid * 16 + lrow, colb);
            ldsm4(aqh, Qh + offq);
            ldsm4(aqm, Qm + offq);
            #pragma unroll
            for (int nb = 0; nb < 4; nb++)
                ldsm4(bk[nb], Ksh + sw_off(nb * 16 + lrow, colb));
            #pragma unroll
            for (int nb = 0; nb < 4; nb++) {
                mma_bf(s[2 * nb],     aqh[0], aqh[1], aqh[2], aqh[3], bk[nb][0], bk[nb][2]);
                mma_bf(s[2 * nb + 1], aqh[0], aqh[1], aqh[2], aqh[3], bk[nb][1], bk[nb][3]);
                mma_bf(s[2 * nb],     aqm[0], aqm[1], aqm[2], aqm[3], bk[nb][0], bk[nb][2]);
                mma_bf(s[2 * nb + 1], aqm[0], aqm[1], aqm[2], aqm[3], bk[nb][1], bk[nb][3]);
            }
            #pragma unroll
            for (int nb = 0; nb < 4; nb++)
                ldsm4(bk[nb], Ksm + sw_off(nb * 16 + lrow, colb));
            #pragma unroll
            for (int nb = 0; nb < 4; nb++) {
                mma_bf(s[2 * nb],     aqh[0], aqh[1], aqh[2], aqh[3], bk[nb][0], bk[nb][2]);
                mma_bf(s[2 * nb + 1], aqh[0], aqh[1], aqh[2], aqh[3], bk[nb][1], bk[nb][3]);
            }
        }

        // ---- scale + relative-position bias (clamped-tile fast path) ----
        {
            bool c0 = false, c1 = false;
            float b0 = 0.f, b1 = 0.f;
            if (kb + 63 - i0 <= -WIN)      { b0 = rLo0; c0 = true; }
            else if (kb - i0 >= WIN)       { b0 = rHi0; c0 = true; }
            if (kb + 63 - i1 <= -WIN)      { b1 = rLo1; c1 = true; }
            else if (kb - i1 >= WIN)       { b1 = rHi1; c1 = true; }
            if (c0 && c1) {
                #pragma unroll
                for (int nf = 0; nf < 8; nf++) {
                    s[nf][0] = fmaf(s[nf][0], 0.125f, b0);
                    s[nf][1] = fmaf(s[nf][1], 0.125f, b0);
                    s[nf][2] = fmaf(s[nf][2], 0.125f, b1);
                    s[nf][3] = fmaf(s[nf][3], 0.125f, b1);
                }
            } else {
                #pragma unroll
                for (int nf = 0; nf < 8; nf++) {
                    const int j = kb + nf * 8 + 2 * t;
                    int d0 = j - i0;       d0 = d0 < -WIN ? -WIN : (d0 > WIN ? WIN : d0);
                    int d0b = j + 1 - i0;  d0b = d0b < -WIN ? -WIN : (d0b > WIN ? WIN : d0b);
                    int d1 = j - i1;       d1 = d1 < -WIN ? -WIN : (d1 > WIN ? WIN : d1);
                    int d1b = j + 1 - i1;  d1b = d1b < -WIN ? -WIN : (d1b > WIN ? WIN : d1b);
                    s[nf][0] = s[nf][0] * 0.125f + __ldg(rpb0 + d0);
                    s[nf][1] = s[nf][1] * 0.125f + __ldg(rpb0 + d0b);
                    s[nf][2] = s[nf][2] * 0.125f + __ldg(rpb1 + d1);
                    s[nf][3] = s[nf][3] * 0.125f + __ldg(rpb1 + d1b);
                }
            }
        }

        // ---- online softmax ----
        float mx0 = -1e30f, mx1 = -1e30f;
        #pragma unroll
        for (int nf = 0; nf < 8; nf++) {
            mx0 = fmaxf(mx0, fmaxf(s[nf][0], s[nf][1]));
            mx1 = fmaxf(mx1, fmaxf(s[nf][2], s[nf][3]));
        }
        mx0 = fmaxf(mx0, __shfl_xor_sync(0xffffffffu, mx0, 1));
        mx0 = fmaxf(mx0, __shfl_xor_sync(0xffffffffu, mx0, 2));
        mx1 = fmaxf(mx1, __shfl_xor_sync(0xffffffffu, mx1, 1));
        mx1 = fmaxf(mx1, __shfl_xor_sync(0xffffffffu, mx1, 2));
        const float mn0 = fmaxf(macc[0], mx0);
        const float mn1 = fmaxf(macc[1], mx1);
        const float cr0 = __expf(macc[0] - mn0);
        const float cr1 = __expf(macc[1] - mn1);
        float sum0 = 0.f, sum1 = 0.f;
        #pragma unroll
        for (int nf = 0; nf < 8; nf++) {
            s[nf][0] = __expf(s[nf][0] - mn0);
            s[nf][1] = __expf(s[nf][1] - mn0);
            s[nf][2] = __expf(s[nf][2] - mn1);
            s[nf][3] = __expf(s[nf][3] - mn1);
            sum0 += s[nf][0] + s[nf][1];
            sum1 += s[nf][2] + s[nf][3];
        }
        sum0 += __shfl_xor_sync(0xffffffffu, sum0, 1);
        sum0 += __shfl_xor_sync(0xffffffffu, sum0, 2);
        sum1 += __shfl_xor_sync(0xffffffffu, sum1, 1);
        sum1 += __shfl_xor_sync(0xffffffffu, sum1, 2);
        lacc[0] = lacc[0] * cr0 + sum0;  macc[0] = mn0;
        lacc[1] = lacc[1] * cr1 + sum1;  macc[1] = mn1;
        #pragma unroll
        for (int nf = 0; nf < 8; nf++) {
            o[nf][0] *= cr0; o[nf][1] *= cr0;
            o[nf][2] *= cr1; o[nf][3] *= cr1;
        }

        uint32_t p0h[8], p0m[8], p1h[8], p1m[8];
        #pragma unroll
        for (int nf = 0; nf < 8; nf++) {
            p0h[nf] = packbf(s[nf][0], s[nf][1]);
            p0m[nf] = packbf(s[nf][0] - unlo(p0h[nf]), s[nf][1] - unhi(p0h[nf]));
            p1h[nf] = packbf(s[nf][2], s[nf][3]);
            p1m[nf] = packbf(s[nf][2] - unlo(p1h[nf]), s[nf][3] - unhi(p1h[nf]));
        }

        #pragma unroll
        for (int kk = 0; kk < 4; kk++) {
            uint32_t bv[4][4];
            const int rowv = kk * 16 + lrow;
            #pragma unroll
            for (int nb = 0; nb < 4; nb++)
                ldsm4t(bv[nb], Vsh + sw_off(rowv, nb * 32 + lcolb));
            const uint32_t a0h = p0h[2 * kk], a1h = p1h[2 * kk];
            const uint32_t a2h = p0h[2 * kk + 1], a3h = p1h[2 * kk + 1];
            const uint32_t a0m = p0m[2 * kk], a1m = p1m[2 * kk];
            const uint32_t a2m = p0m[2 * kk + 1], a3m = p1m[2 * kk + 1];
            #pragma unroll
            for (int nb = 0; nb < 4; nb++) {
                mma_bf(o[2 * nb],     a0h, a1h, a2h, a3h, bv[nb][0], bv[nb][1]);
                mma_bf(o[2 * nb + 1], a0h, a1h, a2h, a3h, bv[nb][2], bv[nb][3]);
                mma_bf(o[2 * nb],     a0m, a1m, a2m, a3m, bv[nb][0], bv[nb][1]);
                mma_bf(o[2 * nb + 1], a0m, a1m, a2m, a3m, bv[nb][2], bv[nb][3]);
            }
            #pragma unroll
            for (int nb = 0; nb < 4; nb++)
                ldsm4t(bv[nb], Vsm + sw_off(rowv, nb * 32 + lcolb));
            #pragma unroll
            for (int nb = 0; nb < 4; nb++) {
                mma_bf(o[2 * nb],     a0h, a1h, a2h, a3h, bv[nb][0], bv[nb][1]);
                mma_bf(o[2 * nb + 1], a0h, a1h, a2h, a3h, bv[nb][2], bv[nb][3]);
            }
        }
        __syncthreads();
    }

    const float inv0 = 1.f / lacc[0];
    const float inv1 = 1.f / lacc[1];
    const int bb = bh >> 4, hh = bh & 15;
    #pragma unroll
    for (int nf = 0; nf < 8; nf++) {
        const int ch = hh * HD + nf * 8 + 2 * t;
        *(float2*)&out[((size_t)(bb * S_LEN + i0)) * D_MODEL + ch] =
            make_float2(o[nf][0] * inv0, o[nf][1] * inv0);
        *(float2*)&out[((size_t)(bb * S_LEN + i1)) * D_MODEL + ch] =
            make_float2(o[nf][2] * inv1, o[nf][3] * inv1);
    }
}

// ---------------------------------------------------------------------------
extern "C" void kernel_launch(void* const* d_in, const int* in_sizes, int n_in,
                              void* d_out, int out_size) {
    (void)in_sizes; (void)n_in; (void)out_size;
    const float* x    = (const float*)d_in[0];
    const float* Wqkv = (const float*)d_in[1];
    const float* bqkv = (const float*)d_in[2];
    const float* Wr   = (const float*)d_in[3];
    const float* br   = (const float*)d_in[4];
    float* out = (float*)d_out;

    uint32_t* xp; cudaGetSymbolAddress((void**)&xp, g_Xp);
    uint32_t* wp; cudaGetSymbolAddress((void**)&wp, g_Wp);
    split_kernel<<<(4096 * 1024 / 4 + 255) / 256, 256>>>(x, xp, 4096 * 1024 / 4);
    split_kernel<<<(3072 * 1024 / 4 + 255) / 256, 256>>>(Wqkv, wp, 3072 * 1024 / 4);
    wr_split_kernel<<<32, 256>>>(Wr);

    cudaFuncSetAttribute(qkv_mma_kernel, cudaFuncAttributeMaxDynamicSharedMemorySize,
                         QKV_SMEM_B);
    qkv_mma_kernel<<<768, 256, QKV_SMEM_B>>>(bqkv);

    cudaFuncSetAttribute(rp_mma_kernel, cudaFuncAttributeMaxDynamicSharedMemorySize,
                         RP_SMEM_B);
    dim3 g2(32, 32);
    rp_mma_kernel<<<g2, 256, RP_SMEM_B>>>(Wr, br);

    cudaFuncSetAttribute(attn_mma_kernel, cudaFuncAttributeMaxDynamicSharedMemorySize,
                         ATT_SMEM_B);
    dim3 g3(16, 32);
    attn_mma_kernel<<<g3, 256, ATT_SMEM_B>>>(out);
}